// round 15
// baseline (speedup 1.0000x reference)
#include <cuda_runtime.h>
#include <cuda_bf16.h>
#include <math.h>
#include <stdint.h>

// ---------------- problem constants ----------------
#define BATCH   4
#define TLEN    2048
#define DMODEL  256
#define NSC     3
#define DM2     512
#define DIN     1024
#define NH      16
#define HD      64
#define DS      128
#define DPROJ   2320     // 2*DIN + 2*DS + NH
#define CCH     1280     // DIN + 2*DS
#define MROWS   (BATCH*TLEN)   // 8192

// ---------------- scratch (device globals; no allocation allowed) ----------------
__device__ float g_xp [(size_t)MROWS*DMODEL];
__device__ float g_pre[(size_t)MROWS*DM2];
__device__ float g_h  [(size_t)MROWS*DM2];
__device__ float g_zx [2][(size_t)MROWS*DPROJ];
__device__ float g_xbc[2][(size_t)MROWS*CCH];
__device__ float g_dt [2][(size_t)MROWS*NH];
__device__ float g_dA [2][(size_t)MROWS*NH];
__device__ float g_y  [2][(size_t)MROWS*DIN];
__device__ float g_od [2][(size_t)MROWS*DM2];
__device__ float g_v  [(size_t)MROWS*DMODEL];

// bf16 hi/lo planes for all GEMM operands
__device__ __nv_bfloat16 g_xgP [2][(size_t)MROWS*768];
__device__ __nv_bfloat16 g_xpP [2][(size_t)MROWS*DMODEL];
__device__ __nv_bfloat16 g_hP2 [2][2][(size_t)MROWS*DM2];   // [plane][dir(0=fwd,1=flipped)]
__device__ __nv_bfloat16 g_yP  [2][2*(size_t)MROWS*DIN];    // [plane][dir*MROWS*DIN + ...]
__device__ __nv_bfloat16 g_uP  [2][(size_t)MROWS*DM2];
__device__ __nv_bfloat16 g_fnP [2][(size_t)MROWS*DMODEL];
__device__ __nv_bfloat16 g_wtP [2][3883008];

// offsets into g_wtP (elements)
#define OFF_WPT    0
#define OFF_WPRET  196608
#define OFF_WINT0  327680
#define OFF_WINT1  1515520
#define OFF_WOUTT0 2703360
#define OFF_WOUTT1 3227648
#define OFF_WPOSTT 3751936

// ---------------- generic helpers ----------------
__device__ __forceinline__ float siluf(float x) { return x / (1.f + __expf(-x)); }

__device__ __forceinline__ void split1(float x, __nv_bfloat16& h, __nv_bfloat16& l) {
    h = __float2bfloat16(x);
    l = __float2bfloat16(x - __bfloat162float(h));
}

// packed f32x2 ops (sm_103a FFMA2 path; only reachable via PTX)
#define FMA2(d, a, b, c) asm("fma.rn.f32x2 %0, %1, %2, %3;" : "=d"(d) : "d"(a), "d"(b), "d"(c))
#define MUL2(d, a, b)    asm("mul.rn.f32x2 %0, %1, %2;"     : "=d"(d) : "d"(a), "d"(b))
#define PACK2(d, lo, hi) asm("mov.b64 %0, {%1, %2};"        : "=d"(d) : "f"(lo), "f"(hi))
#define UNPACK2(lo, hi, s) asm("mov.b64 {%0, %1}, %2;"      : "=f"(lo), "=f"(hi) : "d"(s))

__device__ __forceinline__ float block_reduce(float v) {
    __shared__ float sb[33];
    int lane = threadIdx.x & 31, w = threadIdx.x >> 5;
    #pragma unroll
    for (int o = 16; o; o >>= 1) v += __shfl_xor_sync(0xffffffffu, v, o);
    __syncthreads();
    if (lane == 0) sb[w] = v;
    __syncthreads();
    int nw = blockDim.x >> 5;
    float r = (threadIdx.x < nw) ? sb[threadIdx.x] : 0.f;
    if (w == 0) {
        #pragma unroll
        for (int o = 8; o; o >>= 1) r += __shfl_xor_sync(0xffffffffu, r, o);
        if (lane == 0) sb[32] = r;
    }
    __syncthreads();
    return sb[32];
}

__device__ __forceinline__ void mma_bf16(float c[4], const uint32_t a[4], const uint32_t b[2]) {
    asm volatile("mma.sync.aligned.m16n8k16.row.col.f32.bf16.bf16.f32 "
        "{%0,%1,%2,%3}, {%4,%5,%6,%7}, {%8,%9}, {%0,%1,%2,%3};"
        : "+f"(c[0]), "+f"(c[1]), "+f"(c[2]), "+f"(c[3])
        : "r"(a[0]), "r"(a[1]), "r"(a[2]), "r"(a[3]), "r"(b[0]), "r"(b[1]));
}

__device__ __forceinline__ void ldsm4(uint32_t r[4], uint32_t addr) {
    asm volatile("ldmatrix.sync.aligned.m8n8.x4.shared.b16 {%0,%1,%2,%3}, [%4];"
        : "=r"(r[0]), "=r"(r[1]), "=r"(r[2]), "=r"(r[3]) : "r"(addr));
}

__device__ __forceinline__ void cp16(uint32_t dst, const void* src, int szbytes) {
    asm volatile("cp.async.cg.shared.global [%0], [%1], 16, %2;"
        :: "r"(dst), "l"(src), "r"(szbytes) : "memory");
}
__device__ __forceinline__ void cp8(uint32_t dst, const void* src) {
    asm volatile("cp.async.ca.shared.global [%0], [%1], 8;"
        :: "r"(dst), "l"(src) : "memory");
}
#define CP_COMMIT() asm volatile("cp.async.commit_group;" ::: "memory")
#define CP_WAIT(n)  asm volatile("cp.async.wait_group %0;" :: "n"(n) : "memory")

// ---------------- split-bf16 tensor-core GEMM (64x128 tile, 3 CTAs/SM) ----------
// C[M,N] = A[M,K] @ B[N,K]^T (+bias).  hi*hi + hi*lo + lo*hi, fp32 accum.
// Block tile 64x128, BK=16, 256 threads (8 warps = 2Mx4N of 32x32 warp tiles).
// M % 64 == 0, K % 16 == 0 and K >= 32; N row-guarded.
// Smem: 3 stages x [Ahi 64x12 | Alo | Bhi 128x12 | Blo] words.
#define PLWA  768                  // words per A plane
#define PLWB  1536                 // words per B plane
#define STW   (2*PLWA + 2*PLWB)    // 4608 words per stage
#define SMEM_ALL (3*STW*4)         // 55296 bytes

__global__ void __launch_bounds__(256, 3) tgemmB(
    const __nv_bfloat16* __restrict__ aHg, const __nv_bfloat16* __restrict__ aLg,
    const __nv_bfloat16* __restrict__ bHg, const __nv_bfloat16* __restrict__ bLg,
    const float* __restrict__ bias, float* __restrict__ C,
    __nv_bfloat16* __restrict__ coH, __nv_bfloat16* __restrict__ coL,
    int M, int N, int K, size_t sA, size_t sB, size_t sC)
{
    aHg += (size_t)blockIdx.z * sA;
    aLg += (size_t)blockIdx.z * sA;
    bHg += (size_t)blockIdx.z * sB;
    bLg += (size_t)blockIdx.z * sB;
    C   += (size_t)blockIdx.z * sC;

    extern __shared__ uint32_t sm[];
    const uint32_t smemBase = (uint32_t)__cvta_generic_to_shared(sm);

    const int tid = threadIdx.x;
    const int m0 = blockIdx.y * 64, n0 = blockIdx.x * 128;
    const int lane = tid & 31, w = tid >> 5;
    const int wm = (w & 1) * 32, wn = (w >> 1) * 32;
    const int g = lane >> 2, tq = lane & 3;

    float acc[2][4][4];
    #pragma unroll
    for (int i = 0; i < 2; i++)
        #pragma unroll
        for (int j = 0; j < 4; j++)
            #pragma unroll
            for (int q = 0; q < 4; q++) acc[i][j][q] = 0.f;

    // A load: 64 rows x 16 k -> thread: row tid>>2, 4 bf16 at (tid&3)*4 (8-byte cp)
    const int rA  = tid >> 2;
    const int kqA = (tid & 3) * 4;
    const uint32_t sOffA = (rA*12 + kqA/2) * 4;
    // B load: 128 rows x 16 k -> thread: row tid>>1, 8 bf16 at (tid&1)*8 (16-byte cp)
    const int rB = tid >> 1;
    const int h8 = (tid & 1) * 8;
    const bool bValid = (n0 + rB < N);
    const int bRow = n0 + (bValid ? rB : 0);
    const int bSz = bValid ? 16 : 0;
    const uint32_t sOffB = (rB*12 + h8/2) * 4;

    // ldmatrix per-lane address offsets (bytes)
    const int aoff = ((wm + (lane & 15))*12 + ((lane >> 4) << 2)) * 4;
    const int boff = ((wn + (lane & 7) + ((lane & 16) >> 1))*12 + ((lane & 8) >> 1)) * 4;

    auto issue = [&](int c) {
        const int st = (c % 3);
        const uint32_t base = smemBase + st*STW*4;
        const size_t ak = (size_t)(m0 + rA)*K + (c << 4) + kqA;
        const size_t bk = (size_t)bRow*K + (c << 4) + h8;
        cp8(base                    + sOffA, aHg + ak);
        cp8(base + PLWA*4           + sOffA, aLg + ak);
        cp16(base + 2*PLWA*4          + sOffB, bHg + bk, bSz);
        cp16(base + (2*PLWA+PLWB)*4  + sOffB, bLg + bk, bSz);
    };

    const int nCh = K >> 4;
    issue(0); CP_COMMIT();
    issue(1); CP_COMMIT();

    for (int c = 0; c < nCh; c++) {
        CP_WAIT(1);
        __syncthreads();
        if (c + 2 < nCh) { issue(c + 2); CP_COMMIT(); }

        const int st = (c % 3);
        uint32_t aH = smemBase + st*STW*4 + aoff;
        uint32_t bH = smemBase + st*STW*4 + 2*PLWA*4 + boff;

        uint32_t bh4[2][4], bl4[2][4];
        #pragma unroll
        for (int p2 = 0; p2 < 2; p2++) {
            ldsm4(bh4[p2], bH + p2*768);
            ldsm4(bl4[p2], bH + PLWB*4 + p2*768);
        }
        #pragma unroll
        for (int mi = 0; mi < 2; mi++) {
            uint32_t afh[4], afl[4];
            ldsm4(afh, aH + mi*768);
            ldsm4(afl, aH + PLWA*4 + mi*768);
            #pragma unroll
            for (int ni = 0; ni < 4; ni++) {
                const uint32_t* bhp = &bh4[ni >> 1][(ni & 1)*2];
                const uint32_t* blp = &bl4[ni >> 1][(ni & 1)*2];
                mma_bf16(acc[mi][ni], afh, bhp);
                mma_bf16(acc[mi][ni], afh, blp);
                mma_bf16(acc[mi][ni], afl, bhp);
            }
        }
    }

    #pragma unroll
    for (int mi = 0; mi < 2; mi++) {
        int row = m0 + wm + mi*16 + g;
        #pragma unroll
        for (int ni = 0; ni < 4; ni++) {
            int col = n0 + wn + ni*8 + tq*2;
            if (col < N) {
                float b0v = bias ? bias[col]     : 0.f;
                float b1v = bias ? bias[col + 1] : 0.f;
                float2 v0; v0.x = acc[mi][ni][0] + b0v; v0.y = acc[mi][ni][1] + b1v;
                float2 v1; v1.x = acc[mi][ni][2] + b0v; v1.y = acc[mi][ni][3] + b1v;
                if (C) {
                    *(float2*)(C + (size_t)row*N + col)       = v0;
                    *(float2*)(C + (size_t)(row + 8)*N + col) = v1;
                }
                if (coH) {
                    __nv_bfloat16 hh, ll;
                    split1(v0.x, hh, ll); coH[(size_t)row*N + col]       = hh; coL[(size_t)row*N + col]       = ll;
                    split1(v0.y, hh, ll); coH[(size_t)row*N + col + 1]   = hh; coL[(size_t)row*N + col + 1]   = ll;
                    split1(v1.x, hh, ll); coH[(size_t)(row+8)*N + col]   = hh; coL[(size_t)(row+8)*N + col]   = ll;
                    split1(v1.y, hh, ll); coH[(size_t)(row+8)*N + col+1] = hh; coL[(size_t)(row+8)*N + col+1] = ll;
                }
            }
        }
    }
}

// ---------------- batched weight transpose + split (all 7 weights, ONE launch) --
struct TJobs {
    const float* W[7];
    int K[7], N[7], tX[7], base[7], dstOff[7];
    int total;
};

__global__ void transpose_all_kernel(TJobs jobs,
                                     __nv_bfloat16* __restrict__ WTH,
                                     __nv_bfloat16* __restrict__ WTL) {
    __shared__ float tile[32][33];
    int bid = blockIdx.x;
    int j = 0;
    #pragma unroll
    for (int q = 1; q < 7; q++) if (bid >= jobs.base[q]) j = q;
    int local = bid - jobs.base[j];
    int tX = jobs.tX[j];
    int n0 = (local % tX) * 32;
    int k0 = (local / tX) * 32;
    const float* W = jobs.W[j];
    int K = jobs.K[j], N = jobs.N[j];
    __nv_bfloat16* dH = WTH + jobs.dstOff[j];
    __nv_bfloat16* dL = WTL + jobs.dstOff[j];

    int tx = threadIdx.x, ty = threadIdx.y;   // 32 x 8
    #pragma unroll
    for (int i = ty; i < 32; i += 8)
        if (k0 + i < K && n0 + tx < N) tile[i][tx] = W[(size_t)(k0 + i)*N + n0 + tx];
    __syncthreads();
    #pragma unroll
    for (int i = ty; i < 32; i += 8)
        if (n0 + i < N && k0 + tx < K) {
            __nv_bfloat16 hh, ll;
            split1(tile[tx][i], hh, ll);
            dH[(size_t)(n0 + i)*K + k0 + tx] = hh;
            dL[(size_t)(n0 + i)*K + k0 + tx] = ll;
        }
}

// ---------------- elementwise kernels ----------------
__global__ void gather_kernel(const float* __restrict__ x) {
    size_t idx = (size_t)blockIdx.x * blockDim.x + threadIdx.x;  // MROWS*768 exact
    size_t bt = idx / 768; int r = (int)(idx % 768);
    int s = r >> 8, d = r & 255;
    int b = (int)(bt >> 11), t = (int)(bt & 2047);
    float v = x[(((size_t)(b*NSC + s)*TLEN + t) << 8) + d];
    __nv_bfloat16 hh, ll;
    split1(v, hh, ll);
    g_xgP[0][idx] = hh;
    g_xgP[1][idx] = ll;
}

__global__ void flip_kernel() {
    size_t idx = (size_t)blockIdx.x * blockDim.x + threadIdx.x;  // MROWS*512
    size_t bt = idx >> 9; int j = (int)(idx & 511);
    int b = (int)(bt >> 11), t = (int)(bt & 2047);
    size_t src = (((size_t)(b << 11) | (2047 - t)) << 9) | j;
    g_hP2[0][1][idx] = g_hP2[0][0][src];
    g_hP2[1][1][idx] = g_hP2[1][0][src];
}

__global__ void ln512_kernel(const float* __restrict__ in, const float* __restrict__ g,
                             const float* __restrict__ b, float* __restrict__ out) {
    int row = blockIdx.x, tid = threadIdx.x;
    const float* xr = in + (size_t)row * DM2;
    float v0 = xr[tid], v1 = xr[tid + 256];
    float mu = block_reduce(v0 + v1) * (1.f / 512.f);
    float d0 = v0 - mu, d1 = v1 - mu;
    float var = block_reduce(d0*d0 + d1*d1) * (1.f / 512.f);
    float inv = rsqrtf(var + 1e-5f);
    float o0 = d0 * inv * g[tid]       + b[tid];
    float o1 = d1 * inv * g[tid + 256] + b[tid + 256];
    out[(size_t)row*DM2 + tid]       = o0;
    out[(size_t)row*DM2 + tid + 256] = o1;
    __nv_bfloat16 hh, ll;
    split1(o0, hh, ll);
    g_hP2[0][0][(size_t)row*DM2 + tid] = hh;
    g_hP2[1][0][(size_t)row*DM2 + tid] = ll;
    split1(o1, hh, ll);
    g_hP2[0][0][(size_t)row*DM2 + tid + 256] = hh;
    g_hP2[1][0][(size_t)row*DM2 + tid + 256] = ll;
}

__global__ void conv_kernel(const float* __restrict__ cw0, const float* __restrict__ cb0,
                            const float* __restrict__ cw1, const float* __restrict__ cb1) {
    int dir = blockIdx.y;
    size_t idx = (size_t)blockIdx.x * blockDim.x + threadIdx.x;  // MROWS*CCH
    size_t bt = idx / CCH; int c = (int)(idx % CCH);
    int t = (int)(bt & 2047);
    const float* zx = g_zx[dir];
    const float* cw = dir ? cw1 : cw0;
    const float* cb = dir ? cb1 : cb0;
    float acc = cb[c];
    #pragma unroll
    for (int j = 0; j < 4; j++) {
        int tt = t - 3 + j;
        if (tt >= 0)
            acc += cw[c*4 + j] * zx[(bt + j - 3)*(size_t)DPROJ + DIN + c];
    }
    g_xbc[dir][idx] = siluf(acc);
}

__global__ void dtda_kernel(const float* __restrict__ dtb0, const float* __restrict__ Alog0,
                            const float* __restrict__ dtb1, const float* __restrict__ Alog1) {
    int dir = blockIdx.y;
    size_t idx = (size_t)blockIdx.x * blockDim.x + threadIdx.x;  // MROWS*NH
    size_t row = idx >> 4; int hh = (int)(idx & 15);
    const float* dtb = dir ? dtb1 : dtb0;
    const float* Alog = dir ? Alog1 : Alog0;
    float raw = g_zx[dir][row*(size_t)DPROJ + 2*DIN + 2*DS + hh] + dtb[hh];
    float dtv = (raw > 20.f) ? raw : log1pf(expf(raw));
    float dAv = expf(-expf(Alog[hh]) * dtv);
    g_dt[dir][idx] = dtv;
    g_dA[dir][idx] = dAv;
}

// ---------------- sequential SSM scan (sync-free inner loop, f32x2 packed) -------
#define GP 20
__global__ void __launch_bounds__(512) scan_kernel(
    const float* __restrict__ Dh_f, const float* __restrict__ Dh_b)
{
    int blk = blockIdx.x;
    int dir = blk >> 6;
    int bh  = blk & 63;
    int b = bh >> 4, hh = bh & 15;
    const float* __restrict__ xbc = g_xbc[dir];
    const float* __restrict__ zx  = g_zx[dir];
    const float* __restrict__ dtb = g_dt[dir];
    const float* __restrict__ dAb = g_dA[dir];
    float* __restrict__ yout = g_y[dir];
    float Dval = (dir ? Dh_b : Dh_f)[hh];

    const int tid = threadIdx.x;
    const int p  = tid >> 3;     // 0..63
    const int ng = tid & 7;      // 0..7 -> n = ng*16 .. +15

    double S2[8];
    #pragma unroll
    for (int i = 0; i < 8; i++) S2[i] = 0.0;

    __shared__ float sx[8][64], sz[8][64];
    __shared__ float sB[8][8*GP], sC[8][8*GP];
    __shared__ float sdt[8], sdA[8];
    __shared__ float sy[8][64];

    size_t rowbase = (size_t)b * TLEN;

    for (int c0 = 0; c0 < TLEN; c0 += 8) {
        __syncthreads();
        {
            int t = tid >> 6, pp = tid & 63;
            size_t r = rowbase + c0 + t;
            sx[t][pp] = xbc[r*(size_t)CCH + hh*HD + pp];
            sz[t][pp] = zx [r*(size_t)DPROJ + hh*HD + pp];
        }
        #pragma unroll
        for (int q = 0; q < 2; q++) {
            int idx = tid + q*512;
            int t = idx >> 7, n = idx & 127;
            int off = (n >> 4)*GP + (n & 15);
            size_t r = rowbase + c0 + t;
            sB[t][off] = xbc[r*(size_t)CCH + DIN + n];
            sC[t][off] = xbc[r*(size_t)CCH + DIN + DS + n];
        }
        if (tid < 8) {
            size_t r = rowbase + c0 + tid;
            sdt[tid] = dtb[r*NH + hh];
            sdA[tid] = dAb[r*NH + hh];
        }
        __syncthreads();

        #pragma unroll
        for (int t = 0; t < 8; t++) {
            float dtv = sdt[t], dAv = sdA[t];
            float coef = dtv * sx[t][p];
            double dA2, cf2, pa, pb;
            PACK2(dA2, dAv, dAv);
            PACK2(cf2, coef, coef);
            PACK2(pa, 0.f, 0.f);
            PACK2(pb, 0.f, 0.f);
            const double* B2 = (const double*)&sB[t][ng*GP];
            const double* C2 = (const double*)&sC[t][ng*GP];
            #pragma unroll
            for (int i = 0; i < 4; i++) {
                double2 bb = *(const double2*)(B2 + 2*i);
                double2 cc = *(const double2*)(C2 + 2*i);
                double tmp;
                MUL2(tmp, bb.x, cf2);
                FMA2(S2[2*i],     dA2, S2[2*i],     tmp);
                FMA2(pa, S2[2*i],     cc.x, pa);
                MUL2(tmp, bb.y, cf2);
                FMA2(S2[2*i + 1], dA2, S2[2*i + 1], tmp);
                FMA2(pb, S2[2*i + 1], cc.y, pb);
            }
            float alo, ahi, blo, bhi;
            UNPACK2(alo, ahi, pa);
            UNPACK2(blo, bhi, pb);
            float partial = (alo + ahi) + (blo + bhi);
            partial += __shfl_xor_sync(0xffffffffu, partial, 1);
            partial += __shfl_xor_sync(0xffffffffu, partial, 2);
            partial += __shfl_xor_sync(0xffffffffu, partial, 4);
            if (ng == 0) sy[t][p] = partial;
        }
        __syncthreads();

        {
            int t = tid >> 6, pp = tid & 63;
            float y = sy[t][pp];
            float xv = sx[t][pp];
            float zv = sz[t][pp];
            float yv = (y + Dval * xv) * siluf(zv);
            yout[(rowbase + c0 + t)*(size_t)DIN + hh*HD + pp] = yv;
        }
    }
}

__global__ void rms_kernel(const float* __restrict__ w0, const float* __restrict__ w1,
                           __nv_bfloat16* __restrict__ yH, __nv_bfloat16* __restrict__ yL) {
    int rb = blockIdx.x;                  // 0 .. 2*MROWS-1
    int dir = rb >> 13, row = rb & (MROWS - 1);
    int tid = threadIdx.x;
    const float* yr = g_y[dir] + (size_t)row * DIN;
    const float* w = dir ? w1 : w0;
    size_t obase = (size_t)dir*MROWS*DIN + (size_t)row*DIN;
    float v[4]; float ss = 0.f;
    #pragma unroll
    for (int i = 0; i < 4; i++) { v[i] = yr[tid + i*256]; ss += v[i]*v[i]; }
    ss = block_reduce(ss);
    float inv = rsqrtf(ss * (1.f/1024.f) + 1e-5f);
    #pragma unroll
    for (int i = 0; i < 4; i++) {
        float o = v[i] * inv * w[tid + i*256];
        __nv_bfloat16 hh, ll;
        split1(o, hh, ll);
        yH[obase + tid + i*256] = hh;
        yL[obase + tid + i*256] = ll;
    }
}

__global__ void combine_kernel() {
    size_t idx = (size_t)blockIdx.x * blockDim.x + threadIdx.x;  // MROWS*512
    size_t bt = idx >> 9; int j = (int)(idx & 511);
    int b = (int)(bt >> 11), t = (int)(bt & 2047);
    float hv = g_h[idx];
    float ob = g_od[1][(((size_t)(b << 11) | (2047 - t)) << 9) | j];
    float u = (g_od[0][idx] + ob) * siluf(hv);
    __nv_bfloat16 hh, ll;
    split1(u, hh, ll);
    g_uP[0][idx] = hh;
    g_uP[1][idx] = ll;
}

__global__ void lnpost_kernel(const float* __restrict__ vbuf, const float* __restrict__ g,
                              const float* __restrict__ b, float* __restrict__ outdst) {
    int row = blockIdx.x, tid = threadIdx.x;
    float x = vbuf[(size_t)row*DMODEL + tid];
    float mu = block_reduce(x) * (1.f/256.f);
    float d = x - mu;
    float var = block_reduce(d*d) * (1.f/256.f);
    float o = d * rsqrtf(var + 1e-5f) * g[tid] + b[tid] + g_xp[(size_t)row*DMODEL + tid];
    outdst[(size_t)row*DMODEL + tid] = o;
    float ss = block_reduce(o*o);
    float sc = 1.f / fmaxf(sqrtf(ss), 1e-12f);
    float fnv = o * sc;
    __nv_bfloat16 hh, ll;
    split1(fnv, hh, ll);
    g_fnP[0][(size_t)row*DMODEL + tid] = hh;
    g_fnP[1][(size_t)row*DMODEL + tid] = ll;
}

// ---------------- launcher ----------------
extern "C" void kernel_launch(void* const* d_in, const int* in_sizes, int n_in,
                              void* d_out, int out_size)
{
    const float* x       = (const float*)d_in[0];
    const float* Wp      = (const float*)d_in[1];
    const float* bp      = (const float*)d_in[2];
    const float* Wpre    = (const float*)d_in[3];
    const float* bpre    = (const float*)d_in[4];
    const float* lnpre_g = (const float*)d_in[5];
    const float* lnpre_b = (const float*)d_in[6];
    const float* Wpost   = (const float*)d_in[7];
    const float* bpost   = (const float*)d_in[8];
    const float* lnpost_g= (const float*)d_in[9];
    const float* lnpost_b= (const float*)d_in[10];
    const float* Win[2]   = {(const float*)d_in[11], (const float*)d_in[19]};
    const float* convw[2] = {(const float*)d_in[12], (const float*)d_in[20]};
    const float* convb[2] = {(const float*)d_in[13], (const float*)d_in[21]};
    const float* dtb[2]   = {(const float*)d_in[14], (const float*)d_in[22]};
    const float* Alog[2]  = {(const float*)d_in[15], (const float*)d_in[23]};
    const float* Dh[2]    = {(const float*)d_in[16], (const float*)d_in[24]};
    const float* normw[2] = {(const float*)d_in[17], (const float*)d_in[25]};
    const float* Wout[2]  = {(const float*)d_in[18], (const float*)d_in[26]};

    static bool attr_done = false;
    if (!attr_done) {
        cudaFuncSetAttribute(tgemmB, cudaFuncAttributeMaxDynamicSharedMemorySize, SMEM_ALL);
        attr_done = true;
    }

    float *xp, *pre, *h, *zxb, *odb, *v;
    __nv_bfloat16 *xgP, *xpP, *hP2, *yP, *uP, *fnP, *wtP;
    cudaGetSymbolAddress((void**)&xp,  g_xp);
    cudaGetSymbolAddress((void**)&pre, g_pre);
    cudaGetSymbolAddress((void**)&h,   g_h);
    cudaGetSymbolAddress((void**)&zxb, g_zx);
    cudaGetSymbolAddress((void**)&odb, g_od);
    cudaGetSymbolAddress((void**)&v,   g_v);
    cudaGetSymbolAddress((void**)&xgP, g_xgP);
    cudaGetSymbolAddress((void**)&xpP, g_xpP);
    cudaGetSymbolAddress((void**)&hP2, g_hP2);
    cudaGetSymbolAddress((void**)&yP,  g_yP);
    cudaGetSymbolAddress((void**)&uP,  g_uP);
    cudaGetSymbolAddress((void**)&fnP, g_fnP);
    cudaGetSymbolAddress((void**)&wtP, g_wtP);

    float* zx0 = zxb;
    float* od0 = odb;

    const size_t PXG = (size_t)MROWS*768;
    const size_t PXP = (size_t)MROWS*DMODEL;
    const size_t PH  = (size_t)MROWS*DM2;
    const size_t PY  = 2*(size_t)MROWS*DIN;
    const size_t PW  = 3883008;
    __nv_bfloat16 *xgH = xgP,          *xgL = xgP + PXG;
    __nv_bfloat16 *xpH = xpP,          *xpL = xpP + PXP;
    __nv_bfloat16 *hH  = hP2,          *hL  = hP2 + 2*PH;  // [plane][dir] layout
    __nv_bfloat16 *yH  = yP,           *yL  = yP  + PY;
    __nv_bfloat16 *uH  = uP,           *uL  = uP  + PH;
    __nv_bfloat16 *fnH = fnP,          *fnL = fnP + PXP;
    __nv_bfloat16 *wH  = wtP,          *wL  = wtP + PW;

    float* out  = (float*)d_out;
    float* attn = out + (size_t)MROWS*DMODEL;

    dim3 tb(32, 8);
    // 0. transpose + split all 7 weights in ONE launch
    TJobs jobs;
    const float* Ws[7]   = {Wp, Wpre, Win[0], Win[1], Wout[0], Wout[1], Wpost};
    const int   Ks[7]    = {768, DMODEL, DM2, DM2, DIN, DIN, DM2};
    const int   Ns[7]    = {DMODEL, DM2, DPROJ, DPROJ, DM2, DM2, DMODEL};
    const int   Offs[7]  = {OFF_WPT, OFF_WPRET, OFF_WINT0, OFF_WINT1, OFF_WOUTT0, OFF_WOUTT1, OFF_WPOSTT};
    int base = 0;
    for (int j = 0; j < 7; j++) {
        jobs.W[j] = Ws[j]; jobs.K[j] = Ks[j]; jobs.N[j] = Ns[j];
        jobs.tX[j] = (Ns[j] + 31) / 32;
        jobs.base[j] = base;
        jobs.dstOff[j] = Offs[j];
        base += jobs.tX[j] * ((Ks[j] + 31) / 32);
    }
    jobs.total = base;
    transpose_all_kernel<<<base, tb>>>(jobs, wH, wL);

    // 1. gather (+split) + input projection (epilogue also writes xp planes)
    gather_kernel<<<MROWS*768/256, 256>>>(x);
    tgemmB<<<dim3(2, MROWS/64), 256, SMEM_ALL>>>(
        xgH, xgL, wH + OFF_WPT, wL + OFF_WPT, bp, xp, xpH, xpL, MROWS, DMODEL, 768, 0, 0, 0);
    // 2. pre-layernorm
    tgemmB<<<dim3(4, MROWS/64), 256, SMEM_ALL>>>(
        xpH, xpL, wH + OFF_WPRET, wL + OFF_WPRET, bpre, pre, nullptr, nullptr, MROWS, DM2, DMODEL, 0, 0, 0);
    ln512_kernel<<<MROWS, 256>>>(pre, lnpre_g, lnpre_b, h);
    flip_kernel<<<MROWS*DM2/256, 256>>>();
    // 3. mamba in-projections (both directions in ONE batched launch, z=2)
    tgemmB<<<dim3(19, MROWS/64, 2), 256, SMEM_ALL>>>(
        hH, hL, wH + OFF_WINT0, wL + OFF_WINT0, nullptr, zx0, nullptr, nullptr,
        MROWS, DPROJ, DM2, PH, (size_t)DPROJ*DM2, (size_t)MROWS*DPROJ);
    // 4. conv + dt/dA (both dirs batched)
    conv_kernel<<<dim3(MROWS*CCH/256, 2), 256>>>(convw[0], convb[0], convw[1], convb[1]);
    dtda_kernel<<<dim3(MROWS*NH/256, 2), 256>>>(dtb[0], Alog[0], dtb[1], Alog[1]);
    // 5. both scans concurrently
    scan_kernel<<<128, 512>>>(Dh[0], Dh[1]);
    // 6. RMS-norm (+split, both dirs in one launch) + out-projections (z=2)
    rms_kernel<<<2*MROWS, 256>>>(normw[0], normw[1], yH, yL);
    tgemmB<<<dim3(4, MROWS/64, 2), 256, SMEM_ALL>>>(
        yH, yL, wH + OFF_WOUTT0, wL + OFF_WOUTT0, nullptr, od0, nullptr, nullptr,
        MROWS, DM2, DIN, (size_t)MROWS*DIN, (size_t)DIN*DM2, (size_t)MROWS*DM2);
    // 7. gated combine (+split) + post projection + post-LN(+residual) + fn planes
    combine_kernel<<<MROWS*DM2/256, 256>>>();
    tgemmB<<<dim3(2, MROWS/64), 256, SMEM_ALL>>>(
        uH, uL, wH + OFF_WPOSTT, wL + OFF_WPOSTT, bpost, v, nullptr, nullptr, MROWS, DMODEL, DM2, 0, 0, 0);
    lnpost_kernel<<<MROWS, 256>>>(v, lnpost_g, lnpost_b, out);
    // 8. attn = fn @ fn^T per batch (full)
    tgemmB<<<dim3(16, TLEN/64, BATCH), 256, SMEM_ALL>>>(
        fnH, fnL, fnH, fnL, nullptr, attn, nullptr, nullptr, TLEN, TLEN, DMODEL,
        (size_t)TLEN*DMODEL, (size_t)TLEN*DMODEL, (size_t)TLEN*TLEN);
}

// round 16
// speedup vs baseline: 1.0836x; 1.0836x over previous
#include <cuda_runtime.h>
#include <cuda_bf16.h>
#include <math.h>
#include <stdint.h>

// ---------------- problem constants ----------------
#define BATCH   4
#define TLEN    2048
#define DMODEL  256
#define NSC     3
#define DM2     512
#define DIN     1024
#define NH      16
#define HD      64
#define DS      128
#define DPROJ   2320     // 2*DIN + 2*DS + NH
#define CCH     1280     // DIN + 2*DS
#define MROWS   (BATCH*TLEN)   // 8192

// ---------------- scratch (device globals; no allocation allowed) ----------------
__device__ float g_xp [(size_t)MROWS*DMODEL];
__device__ float g_pre[(size_t)MROWS*DM2];
__device__ float g_h  [(size_t)MROWS*DM2];
__device__ float g_zx [2][(size_t)MROWS*DPROJ];
__device__ float g_xbc[2][(size_t)MROWS*CCH];
__device__ float g_dt [2][(size_t)MROWS*NH];
__device__ float g_dA [2][(size_t)MROWS*NH];
__device__ float g_y  [2][(size_t)MROWS*DIN];
__device__ float g_od [2][(size_t)MROWS*DM2];
__device__ float g_v  [(size_t)MROWS*DMODEL];

// bf16 hi/lo planes for all GEMM operands
__device__ __nv_bfloat16 g_xgP [2][(size_t)MROWS*768];
__device__ __nv_bfloat16 g_xpP [2][(size_t)MROWS*DMODEL];
__device__ __nv_bfloat16 g_hP2 [2][2][(size_t)MROWS*DM2];   // [plane][dir(0=fwd,1=flipped)]
__device__ __nv_bfloat16 g_yP  [2][2*(size_t)MROWS*DIN];    // [plane][dir*MROWS*DIN + ...]
__device__ __nv_bfloat16 g_uP  [2][(size_t)MROWS*DM2];
__device__ __nv_bfloat16 g_fnP [2][(size_t)MROWS*DMODEL];
__device__ __nv_bfloat16 g_wtP [2][3883008];

// offsets into g_wtP (elements)
#define OFF_WPT    0
#define OFF_WPRET  196608
#define OFF_WINT0  327680
#define OFF_WINT1  1515520
#define OFF_WOUTT0 2703360
#define OFF_WOUTT1 3227648
#define OFF_WPOSTT 3751936

// ---------------- generic helpers ----------------
__device__ __forceinline__ float siluf(float x) { return x / (1.f + __expf(-x)); }

__device__ __forceinline__ void split1(float x, __nv_bfloat16& h, __nv_bfloat16& l) {
    h = __float2bfloat16(x);
    l = __float2bfloat16(x - __bfloat162float(h));
}

// packed f32x2 ops (sm_103a FFMA2 path; only reachable via PTX)
#define FMA2(d, a, b, c) asm("fma.rn.f32x2 %0, %1, %2, %3;" : "=d"(d) : "d"(a), "d"(b), "d"(c))
#define MUL2(d, a, b)    asm("mul.rn.f32x2 %0, %1, %2;"     : "=d"(d) : "d"(a), "d"(b))
#define PACK2(d, lo, hi) asm("mov.b64 %0, {%1, %2};"        : "=d"(d) : "f"(lo), "f"(hi))
#define UNPACK2(lo, hi, s) asm("mov.b64 {%0, %1}, %2;"      : "=f"(lo), "=f"(hi) : "d"(s))

__device__ __forceinline__ float block_reduce(float v) {
    __shared__ float sb[33];
    int lane = threadIdx.x & 31, w = threadIdx.x >> 5;
    #pragma unroll
    for (int o = 16; o; o >>= 1) v += __shfl_xor_sync(0xffffffffu, v, o);
    __syncthreads();
    if (lane == 0) sb[w] = v;
    __syncthreads();
    int nw = blockDim.x >> 5;
    float r = (threadIdx.x < nw) ? sb[threadIdx.x] : 0.f;
    if (w == 0) {
        #pragma unroll
        for (int o = 8; o; o >>= 1) r += __shfl_xor_sync(0xffffffffu, r, o);
        if (lane == 0) sb[32] = r;
    }
    __syncthreads();
    return sb[32];
}

__device__ __forceinline__ void mma_bf16(float c[4], const uint32_t a[4], const uint32_t b[2]) {
    asm volatile("mma.sync.aligned.m16n8k16.row.col.f32.bf16.bf16.f32 "
        "{%0,%1,%2,%3}, {%4,%5,%6,%7}, {%8,%9}, {%0,%1,%2,%3};"
        : "+f"(c[0]), "+f"(c[1]), "+f"(c[2]), "+f"(c[3])
        : "r"(a[0]), "r"(a[1]), "r"(a[2]), "r"(a[3]), "r"(b[0]), "r"(b[1]));
}

__device__ __forceinline__ void ldsm4(uint32_t r[4], uint32_t addr) {
    asm volatile("ldmatrix.sync.aligned.m8n8.x4.shared.b16 {%0,%1,%2,%3}, [%4];"
        : "=r"(r[0]), "=r"(r[1]), "=r"(r[2]), "=r"(r[3]) : "r"(addr));
}

__device__ __forceinline__ void cp16(uint32_t dst, const void* src, int szbytes) {
    asm volatile("cp.async.cg.shared.global [%0], [%1], 16, %2;"
        :: "r"(dst), "l"(src), "r"(szbytes) : "memory");
}
#define CP_COMMIT() asm volatile("cp.async.commit_group;" ::: "memory")
#define CP_WAIT(n)  asm volatile("cp.async.wait_group %0;" :: "n"(n) : "memory")

// ---------------- split-bf16 tensor-core GEMM (4-stage pipeline, 2 CTAs/SM) -----
// C[M,N] = A[M,K] @ B[N,K]^T (+bias).  hi*hi + hi*lo + lo*hi, fp32 accum.
// Block tile 128x128, BK=16, 256 threads (8 warps = 2Mx4N of 64x32 warp tiles).
// M % 128 == 0, K % 16 == 0 and K >= 48; N row-guarded.
// Smem: 4 stages x 4 planes (Ahi,Alo,Bhi,Blo), plane = [128 rows][pitch 12 words].
#define PLW   1536                 // words per plane
#define STW   (4*PLW)              // words per stage
#define SMEM_ALL (4*STW*4)         // 98304 bytes

__global__ void __launch_bounds__(256, 2) tgemmB(
    const __nv_bfloat16* __restrict__ aHg, const __nv_bfloat16* __restrict__ aLg,
    const __nv_bfloat16* __restrict__ bHg, const __nv_bfloat16* __restrict__ bLg,
    const float* __restrict__ bias, float* __restrict__ C,
    __nv_bfloat16* __restrict__ coH, __nv_bfloat16* __restrict__ coL,
    int M, int N, int K, size_t sA, size_t sB, size_t sC)
{
    aHg += (size_t)blockIdx.z * sA;
    aLg += (size_t)blockIdx.z * sA;
    bHg += (size_t)blockIdx.z * sB;
    bLg += (size_t)blockIdx.z * sB;
    C   += (size_t)blockIdx.z * sC;

    extern __shared__ uint32_t sm[];
    const uint32_t smemBase = (uint32_t)__cvta_generic_to_shared(sm);

    const int tid = threadIdx.x;
    const int m0 = blockIdx.y * 128, n0 = blockIdx.x * 128;
    const int lane = tid & 31, w = tid >> 5;
    const int wm = (w & 1) * 64, wn = (w >> 1) * 32;
    const int g = lane >> 2, tq = lane & 3;

    float acc[4][4][4];
    #pragma unroll
    for (int i = 0; i < 4; i++)
        #pragma unroll
        for (int j = 0; j < 4; j++)
            #pragma unroll
            for (int q = 0; q < 4; q++) acc[i][j][q] = 0.f;

    // load mapping: thread -> row tid>>1, k-half (tid&1)*8
    const int r = tid >> 1;
    const int h8 = (tid & 1) * 8;
    const bool bValid = (n0 + r < N);
    const int bRow = n0 + (bValid ? r : 0);
    const int bSz = bValid ? 16 : 0;
    const uint32_t sOff = (r*12 + (tid & 1)*4) * 4;   // byte offset in plane

    // ldmatrix per-lane address offsets (bytes)
    const int aoff = ((wm + (lane & 15))*12 + ((lane >> 4) << 2)) * 4;
    const int boff = ((wn + (lane & 7) + ((lane & 16) >> 1))*12 + ((lane & 8) >> 1)) * 4;

    auto issue = [&](int c) {
        const int st = c & 3;
        const size_t ak = (size_t)(m0 + r)*K + (c << 4) + h8;
        const size_t bk = (size_t)bRow*K + (c << 4) + h8;
        const uint32_t base = smemBase + st*STW*4;
        cp16(base             + sOff, aHg + ak, 16);
        cp16(base + PLW*4     + sOff, aLg + ak, 16);
        cp16(base + 2*PLW*4   + sOff, bHg + bk, bSz);
        cp16(base + 3*PLW*4   + sOff, bLg + bk, bSz);
    };

    const int nCh = K >> 4;
    issue(0); CP_COMMIT();
    issue(1); CP_COMMIT();
    issue(2); CP_COMMIT();

    for (int c = 0; c < nCh; c++) {
        CP_WAIT(2);
        __syncthreads();

        const int st = c & 3;
        uint32_t aH = smemBase + st*STW*4 + aoff;
        uint32_t bH = smemBase + st*STW*4 + 2*PLW*4 + boff;

        uint32_t bh4[2][4], bl4[2][4];
        #pragma unroll
        for (int p2 = 0; p2 < 2; p2++) {
            ldsm4(bh4[p2], bH + p2*768);
            ldsm4(bl4[p2], bH + PLW*4 + p2*768);
        }
        #pragma unroll
        for (int mi = 0; mi < 4; mi++) {
            uint32_t afh[4], afl[4];
            ldsm4(afh, aH + mi*768);
            ldsm4(afl, aH + PLW*4 + mi*768);
            // term-major ordering: same-accumulator MMAs are 4 apart, not adjacent
            #pragma unroll
            for (int ni = 0; ni < 4; ni++)
                mma_bf16(acc[mi][ni], afh, &bh4[ni >> 1][(ni & 1)*2]);
            #pragma unroll
            for (int ni = 0; ni < 4; ni++)
                mma_bf16(acc[mi][ni], afh, &bl4[ni >> 1][(ni & 1)*2]);
            #pragma unroll
            for (int ni = 0; ni < 4; ni++)
                mma_bf16(acc[mi][ni], afl, &bh4[ni >> 1][(ni & 1)*2]);
        }

        if (c + 3 < nCh) issue(c + 3);
        CP_COMMIT();
    }

    #pragma unroll
    for (int mi = 0; mi < 4; mi++) {
        int row = m0 + wm + mi*16 + g;
        #pragma unroll
        for (int ni = 0; ni < 4; ni++) {
            int col = n0 + wn + ni*8 + tq*2;
            if (col < N) {
                float b0v = bias ? bias[col]     : 0.f;
                float b1v = bias ? bias[col + 1] : 0.f;
                float2 v0; v0.x = acc[mi][ni][0] + b0v; v0.y = acc[mi][ni][1] + b1v;
                float2 v1; v1.x = acc[mi][ni][2] + b0v; v1.y = acc[mi][ni][3] + b1v;
                if (C) {
                    *(float2*)(C + (size_t)row*N + col)       = v0;
                    *(float2*)(C + (size_t)(row + 8)*N + col) = v1;
                }
                if (coH) {
                    __nv_bfloat16 hh, ll;
                    split1(v0.x, hh, ll); coH[(size_t)row*N + col]       = hh; coL[(size_t)row*N + col]       = ll;
                    split1(v0.y, hh, ll); coH[(size_t)row*N + col + 1]   = hh; coL[(size_t)row*N + col + 1]   = ll;
                    split1(v1.x, hh, ll); coH[(size_t)(row+8)*N + col]   = hh; coL[(size_t)(row+8)*N + col]   = ll;
                    split1(v1.y, hh, ll); coH[(size_t)(row+8)*N + col+1] = hh; coL[(size_t)(row+8)*N + col+1] = ll;
                }
            }
        }
    }
}

// ---------------- batched weight transpose + split (all 7 weights, ONE launch) --
struct TJobs {
    const float* W[7];
    int K[7], N[7], tX[7], base[7], dstOff[7];
    int total;
};

__global__ void transpose_all_kernel(TJobs jobs,
                                     __nv_bfloat16* __restrict__ WTH,
                                     __nv_bfloat16* __restrict__ WTL) {
    __shared__ float tile[32][33];
    int bid = blockIdx.x;
    int j = 0;
    #pragma unroll
    for (int q = 1; q < 7; q++) if (bid >= jobs.base[q]) j = q;
    int local = bid - jobs.base[j];
    int tX = jobs.tX[j];
    int n0 = (local % tX) * 32;
    int k0 = (local / tX) * 32;
    const float* W = jobs.W[j];
    int K = jobs.K[j], N = jobs.N[j];
    __nv_bfloat16* dH = WTH + jobs.dstOff[j];
    __nv_bfloat16* dL = WTL + jobs.dstOff[j];

    int tx = threadIdx.x, ty = threadIdx.y;   // 32 x 8
    #pragma unroll
    for (int i = ty; i < 32; i += 8)
        if (k0 + i < K && n0 + tx < N) tile[i][tx] = W[(size_t)(k0 + i)*N + n0 + tx];
    __syncthreads();
    #pragma unroll
    for (int i = ty; i < 32; i += 8)
        if (n0 + i < N && k0 + tx < K) {
            __nv_bfloat16 hh, ll;
            split1(tile[tx][i], hh, ll);
            dH[(size_t)(n0 + i)*K + k0 + tx] = hh;
            dL[(size_t)(n0 + i)*K + k0 + tx] = ll;
        }
}

// ---------------- elementwise kernels ----------------
__global__ void gather_kernel(const float* __restrict__ x) {
    size_t idx = (size_t)blockIdx.x * blockDim.x + threadIdx.x;  // MROWS*768 exact
    size_t bt = idx / 768; int r = (int)(idx % 768);
    int s = r >> 8, d = r & 255;
    int b = (int)(bt >> 11), t = (int)(bt & 2047);
    float v = x[(((size_t)(b*NSC + s)*TLEN + t) << 8) + d];
    __nv_bfloat16 hh, ll;
    split1(v, hh, ll);
    g_xgP[0][idx] = hh;
    g_xgP[1][idx] = ll;
}

__global__ void flip_kernel() {
    size_t idx = (size_t)blockIdx.x * blockDim.x + threadIdx.x;  // MROWS*512
    size_t bt = idx >> 9; int j = (int)(idx & 511);
    int b = (int)(bt >> 11), t = (int)(bt & 2047);
    size_t src = (((size_t)(b << 11) | (2047 - t)) << 9) | j;
    g_hP2[0][1][idx] = g_hP2[0][0][src];
    g_hP2[1][1][idx] = g_hP2[1][0][src];
}

__global__ void ln512_kernel(const float* __restrict__ in, const float* __restrict__ g,
                             const float* __restrict__ b, float* __restrict__ out) {
    int row = blockIdx.x, tid = threadIdx.x;
    const float* xr = in + (size_t)row * DM2;
    float v0 = xr[tid], v1 = xr[tid + 256];
    float mu = block_reduce(v0 + v1) * (1.f / 512.f);
    float d0 = v0 - mu, d1 = v1 - mu;
    float var = block_reduce(d0*d0 + d1*d1) * (1.f / 512.f);
    float inv = rsqrtf(var + 1e-5f);
    float o0 = d0 * inv * g[tid]       + b[tid];
    float o1 = d1 * inv * g[tid + 256] + b[tid + 256];
    out[(size_t)row*DM2 + tid]       = o0;
    out[(size_t)row*DM2 + tid + 256] = o1;
    __nv_bfloat16 hh, ll;
    split1(o0, hh, ll);
    g_hP2[0][0][(size_t)row*DM2 + tid] = hh;
    g_hP2[1][0][(size_t)row*DM2 + tid] = ll;
    split1(o1, hh, ll);
    g_hP2[0][0][(size_t)row*DM2 + tid + 256] = hh;
    g_hP2[1][0][(size_t)row*DM2 + tid + 256] = ll;
}

__global__ void conv_kernel(const float* __restrict__ cw0, const float* __restrict__ cb0,
                            const float* __restrict__ cw1, const float* __restrict__ cb1) {
    int dir = blockIdx.y;
    size_t idx = (size_t)blockIdx.x * blockDim.x + threadIdx.x;  // MROWS*CCH
    size_t bt = idx / CCH; int c = (int)(idx % CCH);
    int t = (int)(bt & 2047);
    const float* zx = g_zx[dir];
    const float* cw = dir ? cw1 : cw0;
    const float* cb = dir ? cb1 : cb0;
    float acc = cb[c];
    #pragma unroll
    for (int j = 0; j < 4; j++) {
        int tt = t - 3 + j;
        if (tt >= 0)
            acc += cw[c*4 + j] * zx[(bt + j - 3)*(size_t)DPROJ + DIN + c];
    }
    g_xbc[dir][idx] = siluf(acc);
}

__global__ void dtda_kernel(const float* __restrict__ dtb0, const float* __restrict__ Alog0,
                            const float* __restrict__ dtb1, const float* __restrict__ Alog1) {
    int dir = blockIdx.y;
    size_t idx = (size_t)blockIdx.x * blockDim.x + threadIdx.x;  // MROWS*NH
    size_t row = idx >> 4; int hh = (int)(idx & 15);
    const float* dtb = dir ? dtb1 : dtb0;
    const float* Alog = dir ? Alog1 : Alog0;
    float raw = g_zx[dir][row*(size_t)DPROJ + 2*DIN + 2*DS + hh] + dtb[hh];
    float dtv = (raw > 20.f) ? raw : log1pf(expf(raw));
    float dAv = expf(-expf(Alog[hh]) * dtv);
    g_dt[dir][idx] = dtv;
    g_dA[dir][idx] = dAv;
}

// ---------------- sequential SSM scan (sync-free inner loop, f32x2 packed) -------
#define GP 20
__global__ void __launch_bounds__(512) scan_kernel(
    const float* __restrict__ Dh_f, const float* __restrict__ Dh_b)
{
    int blk = blockIdx.x;
    int dir = blk >> 6;
    int bh  = blk & 63;
    int b = bh >> 4, hh = bh & 15;
    const float* __restrict__ xbc = g_xbc[dir];
    const float* __restrict__ zx  = g_zx[dir];
    const float* __restrict__ dtb = g_dt[dir];
    const float* __restrict__ dAb = g_dA[dir];
    float* __restrict__ yout = g_y[dir];
    float Dval = (dir ? Dh_b : Dh_f)[hh];

    const int tid = threadIdx.x;
    const int p  = tid >> 3;     // 0..63
    const int ng = tid & 7;      // 0..7 -> n = ng*16 .. +15

    double S2[8];
    #pragma unroll
    for (int i = 0; i < 8; i++) S2[i] = 0.0;

    __shared__ float sx[8][64], sz[8][64];
    __shared__ float sB[8][8*GP], sC[8][8*GP];
    __shared__ float sdt[8], sdA[8];
    __shared__ float sy[8][64];

    size_t rowbase = (size_t)b * TLEN;

    for (int c0 = 0; c0 < TLEN; c0 += 8) {
        __syncthreads();
        {
            int t = tid >> 6, pp = tid & 63;
            size_t r = rowbase + c0 + t;
            sx[t][pp] = xbc[r*(size_t)CCH + hh*HD + pp];
            sz[t][pp] = zx [r*(size_t)DPROJ + hh*HD + pp];
        }
        #pragma unroll
        for (int q = 0; q < 2; q++) {
            int idx = tid + q*512;
            int t = idx >> 7, n = idx & 127;
            int off = (n >> 4)*GP + (n & 15);
            size_t r = rowbase + c0 + t;
            sB[t][off] = xbc[r*(size_t)CCH + DIN + n];
            sC[t][off] = xbc[r*(size_t)CCH + DIN + DS + n];
        }
        if (tid < 8) {
            size_t r = rowbase + c0 + tid;
            sdt[tid] = dtb[r*NH + hh];
            sdA[tid] = dAb[r*NH + hh];
        }
        __syncthreads();

        #pragma unroll
        for (int t = 0; t < 8; t++) {
            float dtv = sdt[t], dAv = sdA[t];
            float coef = dtv * sx[t][p];
            double dA2, cf2, pa, pb;
            PACK2(dA2, dAv, dAv);
            PACK2(cf2, coef, coef);
            PACK2(pa, 0.f, 0.f);
            PACK2(pb, 0.f, 0.f);
            const double* B2 = (const double*)&sB[t][ng*GP];
            const double* C2 = (const double*)&sC[t][ng*GP];
            #pragma unroll
            for (int i = 0; i < 4; i++) {
                double2 bb = *(const double2*)(B2 + 2*i);
                double2 cc = *(const double2*)(C2 + 2*i);
                double tmp;
                MUL2(tmp, bb.x, cf2);
                FMA2(S2[2*i],     dA2, S2[2*i],     tmp);
                FMA2(pa, S2[2*i],     cc.x, pa);
                MUL2(tmp, bb.y, cf2);
                FMA2(S2[2*i + 1], dA2, S2[2*i + 1], tmp);
                FMA2(pb, S2[2*i + 1], cc.y, pb);
            }
            float alo, ahi, blo, bhi;
            UNPACK2(alo, ahi, pa);
            UNPACK2(blo, bhi, pb);
            float partial = (alo + ahi) + (blo + bhi);
            partial += __shfl_xor_sync(0xffffffffu, partial, 1);
            partial += __shfl_xor_sync(0xffffffffu, partial, 2);
            partial += __shfl_xor_sync(0xffffffffu, partial, 4);
            if (ng == 0) sy[t][p] = partial;
        }
        __syncthreads();

        {
            int t = tid >> 6, pp = tid & 63;
            float y = sy[t][pp];
            float xv = sx[t][pp];
            float zv = sz[t][pp];
            float yv = (y + Dval * xv) * siluf(zv);
            yout[(rowbase + c0 + t)*(size_t)DIN + hh*HD + pp] = yv;
        }
    }
}

__global__ void rms_kernel(const float* __restrict__ w0, const float* __restrict__ w1,
                           __nv_bfloat16* __restrict__ yH, __nv_bfloat16* __restrict__ yL) {
    int rb = blockIdx.x;                  // 0 .. 2*MROWS-1
    int dir = rb >> 13, row = rb & (MROWS - 1);
    int tid = threadIdx.x;
    const float* yr = g_y[dir] + (size_t)row * DIN;
    const float* w = dir ? w1 : w0;
    size_t obase = (size_t)dir*MROWS*DIN + (size_t)row*DIN;
    float v[4]; float ss = 0.f;
    #pragma unroll
    for (int i = 0; i < 4; i++) { v[i] = yr[tid + i*256]; ss += v[i]*v[i]; }
    ss = block_reduce(ss);
    float inv = rsqrtf(ss * (1.f/1024.f) + 1e-5f);
    #pragma unroll
    for (int i = 0; i < 4; i++) {
        float o = v[i] * inv * w[tid + i*256];
        __nv_bfloat16 hh, ll;
        split1(o, hh, ll);
        yH[obase + tid + i*256] = hh;
        yL[obase + tid + i*256] = ll;
    }
}

__global__ void combine_kernel() {
    size_t idx = (size_t)blockIdx.x * blockDim.x + threadIdx.x;  // MROWS*512
    size_t bt = idx >> 9; int j = (int)(idx & 511);
    int b = (int)(bt >> 11), t = (int)(bt & 2047);
    float hv = g_h[idx];
    float ob = g_od[1][(((size_t)(b << 11) | (2047 - t)) << 9) | j];
    float u = (g_od[0][idx] + ob) * siluf(hv);
    __nv_bfloat16 hh, ll;
    split1(u, hh, ll);
    g_uP[0][idx] = hh;
    g_uP[1][idx] = ll;
}

__global__ void lnpost_kernel(const float* __restrict__ vbuf, const float* __restrict__ g,
                              const float* __restrict__ b, float* __restrict__ outdst) {
    int row = blockIdx.x, tid = threadIdx.x;
    float x = vbuf[(size_t)row*DMODEL + tid];
    float mu = block_reduce(x) * (1.f/256.f);
    float d = x - mu;
    float var = block_reduce(d*d) * (1.f/256.f);
    float o = d * rsqrtf(var + 1e-5f) * g[tid] + b[tid] + g_xp[(size_t)row*DMODEL + tid];
    outdst[(size_t)row*DMODEL + tid] = o;
    float ss = block_reduce(o*o);
    float sc = 1.f / fmaxf(sqrtf(ss), 1e-12f);
    float fnv = o * sc;
    __nv_bfloat16 hh, ll;
    split1(fnv, hh, ll);
    g_fnP[0][(size_t)row*DMODEL + tid] = hh;
    g_fnP[1][(size_t)row*DMODEL + tid] = ll;
}

// ---------------- launcher ----------------
extern "C" void kernel_launch(void* const* d_in, const int* in_sizes, int n_in,
                              void* d_out, int out_size)
{
    const float* x       = (const float*)d_in[0];
    const float* Wp      = (const float*)d_in[1];
    const float* bp      = (const float*)d_in[2];
    const float* Wpre    = (const float*)d_in[3];
    const float* bpre    = (const float*)d_in[4];
    const float* lnpre_g = (const float*)d_in[5];
    const float* lnpre_b = (const float*)d_in[6];
    const float* Wpost   = (const float*)d_in[7];
    const float* bpost   = (const float*)d_in[8];
    const float* lnpost_g= (const float*)d_in[9];
    const float* lnpost_b= (const float*)d_in[10];
    const float* Win[2]   = {(const float*)d_in[11], (const float*)d_in[19]};
    const float* convw[2] = {(const float*)d_in[12], (const float*)d_in[20]};
    const float* convb[2] = {(const float*)d_in[13], (const float*)d_in[21]};
    const float* dtb[2]   = {(const float*)d_in[14], (const float*)d_in[22]};
    const float* Alog[2]  = {(const float*)d_in[15], (const float*)d_in[23]};
    const float* Dh[2]    = {(const float*)d_in[16], (const float*)d_in[24]};
    const float* normw[2] = {(const float*)d_in[17], (const float*)d_in[25]};
    const float* Wout[2]  = {(const float*)d_in[18], (const float*)d_in[26]};

    static bool attr_done = false;
    if (!attr_done) {
        cudaFuncSetAttribute(tgemmB, cudaFuncAttributeMaxDynamicSharedMemorySize, SMEM_ALL);
        attr_done = true;
    }

    float *xp, *pre, *h, *zxb, *odb, *v;
    __nv_bfloat16 *xgP, *xpP, *hP2, *yP, *uP, *fnP, *wtP;
    cudaGetSymbolAddress((void**)&xp,  g_xp);
    cudaGetSymbolAddress((void**)&pre, g_pre);
    cudaGetSymbolAddress((void**)&h,   g_h);
    cudaGetSymbolAddress((void**)&zxb, g_zx);
    cudaGetSymbolAddress((void**)&odb, g_od);
    cudaGetSymbolAddress((void**)&v,   g_v);
    cudaGetSymbolAddress((void**)&xgP, g_xgP);
    cudaGetSymbolAddress((void**)&xpP, g_xpP);
    cudaGetSymbolAddress((void**)&hP2, g_hP2);
    cudaGetSymbolAddress((void**)&yP,  g_yP);
    cudaGetSymbolAddress((void**)&uP,  g_uP);
    cudaGetSymbolAddress((void**)&fnP, g_fnP);
    cudaGetSymbolAddress((void**)&wtP, g_wtP);

    float* zx0 = zxb;
    float* od0 = odb;

    const size_t PXG = (size_t)MROWS*768;
    const size_t PXP = (size_t)MROWS*DMODEL;
    const size_t PH  = (size_t)MROWS*DM2;
    const size_t PY  = 2*(size_t)MROWS*DIN;
    const size_t PW  = 3883008;
    __nv_bfloat16 *xgH = xgP,          *xgL = xgP + PXG;
    __nv_bfloat16 *xpH = xpP,          *xpL = xpP + PXP;
    __nv_bfloat16 *hH  = hP2,          *hL  = hP2 + 2*PH;  // [plane][dir] layout
    __nv_bfloat16 *yH  = yP,           *yL  = yP  + PY;
    __nv_bfloat16 *uH  = uP,           *uL  = uP  + PH;
    __nv_bfloat16 *fnH = fnP,          *fnL = fnP + PXP;
    __nv_bfloat16 *wH  = wtP,          *wL  = wtP + PW;

    float* out  = (float*)d_out;
    float* attn = out + (size_t)MROWS*DMODEL;

    dim3 tb(32, 8);
    // 0. transpose + split all 7 weights in ONE launch
    TJobs jobs;
    const float* Ws[7]   = {Wp, Wpre, Win[0], Win[1], Wout[0], Wout[1], Wpost};
    const int   Ks[7]    = {768, DMODEL, DM2, DM2, DIN, DIN, DM2};
    const int   Ns[7]    = {DMODEL, DM2, DPROJ, DPROJ, DM2, DM2, DMODEL};
    const int   Offs[7]  = {OFF_WPT, OFF_WPRET, OFF_WINT0, OFF_WINT1, OFF_WOUTT0, OFF_WOUTT1, OFF_WPOSTT};
    int base = 0;
    for (int j = 0; j < 7; j++) {
        jobs.W[j] = Ws[j]; jobs.K[j] = Ks[j]; jobs.N[j] = Ns[j];
        jobs.tX[j] = (Ns[j] + 31) / 32;
        jobs.base[j] = base;
        jobs.dstOff[j] = Offs[j];
        base += jobs.tX[j] * ((Ks[j] + 31) / 32);
    }
    jobs.total = base;
    transpose_all_kernel<<<base, tb>>>(jobs, wH, wL);

    // 1. gather (+split) + input projection (epilogue also writes xp planes)
    gather_kernel<<<MROWS*768/256, 256>>>(x);
    tgemmB<<<dim3(2, MROWS/128), 256, SMEM_ALL>>>(
        xgH, xgL, wH + OFF_WPT, wL + OFF_WPT, bp, xp, xpH, xpL, MROWS, DMODEL, 768, 0, 0, 0);
    // 2. pre-layernorm
    tgemmB<<<dim3(4, MROWS/128), 256, SMEM_ALL>>>(
        xpH, xpL, wH + OFF_WPRET, wL + OFF_WPRET, bpre, pre, nullptr, nullptr, MROWS, DM2, DMODEL, 0, 0, 0);
    ln512_kernel<<<MROWS, 256>>>(pre, lnpre_g, lnpre_b, h);
    flip_kernel<<<MROWS*DM2/256, 256>>>();
    // 3. mamba in-projections (both directions in ONE batched launch, z=2)
    tgemmB<<<dim3(19, MROWS/128, 2), 256, SMEM_ALL>>>(
        hH, hL, wH + OFF_WINT0, wL + OFF_WINT0, nullptr, zx0, nullptr, nullptr,
        MROWS, DPROJ, DM2, PH, (size_t)DPROJ*DM2, (size_t)MROWS*DPROJ);
    // 4. conv + dt/dA (both dirs batched)
    conv_kernel<<<dim3(MROWS*CCH/256, 2), 256>>>(convw[0], convb[0], convw[1], convb[1]);
    dtda_kernel<<<dim3(MROWS*NH/256, 2), 256>>>(dtb[0], Alog[0], dtb[1], Alog[1]);
    // 5. both scans concurrently
    scan_kernel<<<128, 512>>>(Dh[0], Dh[1]);
    // 6. RMS-norm (+split, both dirs in one launch) + out-projections (z=2)
    rms_kernel<<<2*MROWS, 256>>>(normw[0], normw[1], yH, yL);
    tgemmB<<<dim3(4, MROWS/128, 2), 256, SMEM_ALL>>>(
        yH, yL, wH + OFF_WOUTT0, wL + OFF_WOUTT0, nullptr, od0, nullptr, nullptr,
        MROWS, DM2, DIN, (size_t)MROWS*DIN, (size_t)DIN*DM2, (size_t)MROWS*DM2);
    // 7. gated combine (+split) + post projection + post-LN(+residual) + fn planes
    combine_kernel<<<MROWS*DM2/256, 256>>>();
    tgemmB<<<dim3(2, MROWS/128), 256, SMEM_ALL>>>(
        uH, uL, wH + OFF_WPOSTT, wL + OFF_WPOSTT, bpost, v, nullptr, nullptr, MROWS, DMODEL, DM2, 0, 0, 0);
    lnpost_kernel<<<MROWS, 256>>>(v, lnpost_g, lnpost_b, out);
    // 8. attn = fn @ fn^T per batch (full)
    tgemmB<<<dim3(16, 16, BATCH), 256, SMEM_ALL>>>(
        fnH, fnL, fnH, fnL, nullptr, attn, nullptr, nullptr, TLEN, TLEN, DMODEL,
        (size_t)TLEN*DMODEL, (size_t)TLEN*DMODEL, (size_t)TLEN*TLEN);
}

// round 17
// speedup vs baseline: 1.1075x; 1.0221x over previous
#include <cuda_runtime.h>
#include <cuda_bf16.h>
#include <math.h>
#include <stdint.h>

// ---------------- problem constants ----------------
#define BATCH   4
#define TLEN    2048
#define DMODEL  256
#define NSC     3
#define DM2     512
#define DIN     1024
#define NH      16
#define HD      64
#define DS      128
#define DPROJ   2320     // 2*DIN + 2*DS + NH
#define CCH     1280     // DIN + 2*DS
#define MROWS   (BATCH*TLEN)   // 8192

// ---------------- scratch (device globals; no allocation allowed) ----------------
__device__ float g_xp [(size_t)MROWS*DMODEL];
__device__ float g_pre[(size_t)MROWS*DM2];
__device__ float g_h  [(size_t)MROWS*DM2];
__device__ float g_zx [2][(size_t)MROWS*DPROJ];
__device__ float g_xbc[2][(size_t)MROWS*CCH];
__device__ float g_dt [2][(size_t)MROWS*NH];
__device__ float g_dA [2][(size_t)MROWS*NH];
__device__ float g_y  [2][(size_t)MROWS*DIN];
__device__ float g_od [2][(size_t)MROWS*DM2];
__device__ float g_v  [(size_t)MROWS*DMODEL];

// bf16 hi/lo planes for all GEMM operands
__device__ __nv_bfloat16 g_xgP [2][(size_t)MROWS*768];
__device__ __nv_bfloat16 g_xpP [2][(size_t)MROWS*DMODEL];
__device__ __nv_bfloat16 g_hP2 [2][2][(size_t)MROWS*DM2];   // [plane][dir(0=fwd,1=flipped)]
__device__ __nv_bfloat16 g_yP  [2][2*(size_t)MROWS*DIN];    // [plane][dir*MROWS*DIN + ...]
__device__ __nv_bfloat16 g_uP  [2][(size_t)MROWS*DM2];
__device__ __nv_bfloat16 g_fnP [2][(size_t)MROWS*DMODEL];
__device__ __nv_bfloat16 g_wtP [2][3883008];

// offsets into g_wtP (elements)
#define OFF_WPT    0
#define OFF_WPRET  196608
#define OFF_WINT0  327680
#define OFF_WINT1  1515520
#define OFF_WOUTT0 2703360
#define OFF_WOUTT1 3227648
#define OFF_WPOSTT 3751936

// ---------------- generic helpers ----------------
__device__ __forceinline__ float siluf(float x) { return x / (1.f + __expf(-x)); }

__device__ __forceinline__ void split1(float x, __nv_bfloat16& h, __nv_bfloat16& l) {
    h = __float2bfloat16(x);
    l = __float2bfloat16(x - __bfloat162float(h));
}

// packed f32x2 ops (sm_103a FFMA2 path; only reachable via PTX)
#define FMA2(d, a, b, c) asm("fma.rn.f32x2 %0, %1, %2, %3;" : "=d"(d) : "d"(a), "d"(b), "d"(c))
#define MUL2(d, a, b)    asm("mul.rn.f32x2 %0, %1, %2;"     : "=d"(d) : "d"(a), "d"(b))
#define PACK2(d, lo, hi) asm("mov.b64 %0, {%1, %2};"        : "=d"(d) : "f"(lo), "f"(hi))
#define UNPACK2(lo, hi, s) asm("mov.b64 {%0, %1}, %2;"      : "=f"(lo), "=f"(hi) : "d"(s))

__device__ __forceinline__ float block_reduce(float v) {
    __shared__ float sb[33];
    int lane = threadIdx.x & 31, w = threadIdx.x >> 5;
    #pragma unroll
    for (int o = 16; o; o >>= 1) v += __shfl_xor_sync(0xffffffffu, v, o);
    __syncthreads();
    if (lane == 0) sb[w] = v;
    __syncthreads();
    int nw = blockDim.x >> 5;
    float r = (threadIdx.x < nw) ? sb[threadIdx.x] : 0.f;
    if (w == 0) {
        #pragma unroll
        for (int o = 8; o; o >>= 1) r += __shfl_xor_sync(0xffffffffu, r, o);
        if (lane == 0) sb[32] = r;
    }
    __syncthreads();
    return sb[32];
}

__device__ __forceinline__ void mma_bf16(float c[4], const uint32_t a[4], const uint32_t b[2]) {
    asm volatile("mma.sync.aligned.m16n8k16.row.col.f32.bf16.bf16.f32 "
        "{%0,%1,%2,%3}, {%4,%5,%6,%7}, {%8,%9}, {%0,%1,%2,%3};"
        : "+f"(c[0]), "+f"(c[1]), "+f"(c[2]), "+f"(c[3])
        : "r"(a[0]), "r"(a[1]), "r"(a[2]), "r"(a[3]), "r"(b[0]), "r"(b[1]));
}

__device__ __forceinline__ void ldsm4(uint32_t r[4], uint32_t addr) {
    asm volatile("ldmatrix.sync.aligned.m8n8.x4.shared.b16 {%0,%1,%2,%3}, [%4];"
        : "=r"(r[0]), "=r"(r[1]), "=r"(r[2]), "=r"(r[3]) : "r"(addr));
}

__device__ __forceinline__ void cp16(uint32_t dst, const void* src, int szbytes) {
    asm volatile("cp.async.cg.shared.global [%0], [%1], 16, %2;"
        :: "r"(dst), "l"(src), "r"(szbytes) : "memory");
}
#define CP_COMMIT() asm volatile("cp.async.commit_group;" ::: "memory")
#define CP_WAIT(n)  asm volatile("cp.async.wait_group %0;" :: "n"(n) : "memory")

// ---------------- split-bf16 tensor-core GEMM (4-stage pipeline, 2 CTAs/SM) -----
// C[M,N] = A[M,K] @ B[N,K]^T (+bias).  hi*hi + hi*lo + lo*hi, fp32 accum.
// Block tile 128x128, BK=16, 256 threads (8 warps = 2Mx4N of 64x32 warp tiles).
// M % 128 == 0, K % 16 == 0 and K >= 48; N row-guarded.
// sym=1 (square symmetric C): blocks bx<by skipped; bx>by blocks also write the
// mirrored block via an smem transpose (coalesced stores). No separate pass.
// Smem: 4 stages x 4 planes (Ahi,Alo,Bhi,Blo), plane = [128 rows][pitch 12 words].
#define PLW   1536                 // words per plane
#define STW   (4*PLW)              // words per stage
#define SMEM_ALL (4*STW*4)         // 98304 bytes

__global__ void __launch_bounds__(256, 2) tgemmB(
    const __nv_bfloat16* __restrict__ aHg, const __nv_bfloat16* __restrict__ aLg,
    const __nv_bfloat16* __restrict__ bHg, const __nv_bfloat16* __restrict__ bLg,
    const float* __restrict__ bias, float* __restrict__ C,
    __nv_bfloat16* __restrict__ coH, __nv_bfloat16* __restrict__ coL,
    int M, int N, int K, size_t sA, size_t sB, size_t sC, int sym)
{
    if (sym && (int)blockIdx.x < (int)blockIdx.y) return;
    aHg += (size_t)blockIdx.z * sA;
    aLg += (size_t)blockIdx.z * sA;
    bHg += (size_t)blockIdx.z * sB;
    bLg += (size_t)blockIdx.z * sB;
    C   += (size_t)blockIdx.z * sC;

    extern __shared__ uint32_t sm[];
    const uint32_t smemBase = (uint32_t)__cvta_generic_to_shared(sm);

    const int tid = threadIdx.x;
    const int m0 = blockIdx.y * 128, n0 = blockIdx.x * 128;
    const int lane = tid & 31, w = tid >> 5;
    const int wm = (w & 1) * 64, wn = (w >> 1) * 32;
    const int g = lane >> 2, tq = lane & 3;

    float acc[4][4][4];
    #pragma unroll
    for (int i = 0; i < 4; i++)
        #pragma unroll
        for (int j = 0; j < 4; j++)
            #pragma unroll
            for (int q = 0; q < 4; q++) acc[i][j][q] = 0.f;

    // load mapping: thread -> row tid>>1, k-half (tid&1)*8
    const int r = tid >> 1;
    const int h8 = (tid & 1) * 8;
    const bool bValid = (n0 + r < N);
    const int bRow = n0 + (bValid ? r : 0);
    const int bSz = bValid ? 16 : 0;
    const uint32_t sOff = (r*12 + (tid & 1)*4) * 4;   // byte offset in plane

    // ldmatrix per-lane address offsets (bytes)
    const int aoff = ((wm + (lane & 15))*12 + ((lane >> 4) << 2)) * 4;
    const int boff = ((wn + (lane & 7) + ((lane & 16) >> 1))*12 + ((lane & 8) >> 1)) * 4;

    auto issue = [&](int c) {
        const int st = c & 3;
        const size_t ak = (size_t)(m0 + r)*K + (c << 4) + h8;
        const size_t bk = (size_t)bRow*K + (c << 4) + h8;
        const uint32_t base = smemBase + st*STW*4;
        cp16(base             + sOff, aHg + ak, 16);
        cp16(base + PLW*4     + sOff, aLg + ak, 16);
        cp16(base + 2*PLW*4   + sOff, bHg + bk, bSz);
        cp16(base + 3*PLW*4   + sOff, bLg + bk, bSz);
    };

    const int nCh = K >> 4;
    issue(0); CP_COMMIT();
    issue(1); CP_COMMIT();
    issue(2); CP_COMMIT();

    for (int c = 0; c < nCh; c++) {
        CP_WAIT(2);
        __syncthreads();

        const int st = c & 3;
        uint32_t aH = smemBase + st*STW*4 + aoff;
        uint32_t bH = smemBase + st*STW*4 + 2*PLW*4 + boff;

        uint32_t bh4[2][4], bl4[2][4];
        #pragma unroll
        for (int p2 = 0; p2 < 2; p2++) {
            ldsm4(bh4[p2], bH + p2*768);
            ldsm4(bl4[p2], bH + PLW*4 + p2*768);
        }
        #pragma unroll
        for (int mi = 0; mi < 4; mi++) {
            uint32_t afh[4], afl[4];
            ldsm4(afh, aH + mi*768);
            ldsm4(afl, aH + PLW*4 + mi*768);
            #pragma unroll
            for (int ni = 0; ni < 4; ni++) {
                const uint32_t* bhp = &bh4[ni >> 1][(ni & 1)*2];
                const uint32_t* blp = &bl4[ni >> 1][(ni & 1)*2];
                mma_bf16(acc[mi][ni], afh, bhp);
                mma_bf16(acc[mi][ni], afh, blp);
                mma_bf16(acc[mi][ni], afl, bhp);
            }
        }

        if (c + 3 < nCh) issue(c + 3);
        CP_COMMIT();
    }

    // direct block write (+ optional bf16 plane split)
    #pragma unroll
    for (int mi = 0; mi < 4; mi++) {
        int row = m0 + wm + mi*16 + g;
        #pragma unroll
        for (int ni = 0; ni < 4; ni++) {
            int col = n0 + wn + ni*8 + tq*2;
            if (col < N) {
                float b0v = bias ? bias[col]     : 0.f;
                float b1v = bias ? bias[col + 1] : 0.f;
                float2 v0; v0.x = acc[mi][ni][0] + b0v; v0.y = acc[mi][ni][1] + b1v;
                float2 v1; v1.x = acc[mi][ni][2] + b0v; v1.y = acc[mi][ni][3] + b1v;
                if (C) {
                    *(float2*)(C + (size_t)row*N + col)       = v0;
                    *(float2*)(C + (size_t)(row + 8)*N + col) = v1;
                }
                if (coH) {
                    __nv_bfloat16 hh, ll;
                    split1(v0.x, hh, ll); coH[(size_t)row*N + col]       = hh; coL[(size_t)row*N + col]       = ll;
                    split1(v0.y, hh, ll); coH[(size_t)row*N + col + 1]   = hh; coL[(size_t)row*N + col + 1]   = ll;
                    split1(v1.x, hh, ll); coH[(size_t)(row+8)*N + col]   = hh; coL[(size_t)(row+8)*N + col]   = ll;
                    split1(v1.y, hh, ll); coH[(size_t)(row+8)*N + col+1] = hh; coL[(size_t)(row+8)*N + col+1] = ll;
                }
            }
        }
    }

    // mirrored block write via smem transpose (symmetric output, off-diagonal)
    if (sym && blockIdx.x != blockIdx.y) {
        __syncthreads();           // mainloop smem no longer needed
        float* ts = (float*)sm;    // [128][129] floats = 66048 B
        #pragma unroll
        for (int mi = 0; mi < 4; mi++) {
            int rl = wm + mi*16 + g;
            #pragma unroll
            for (int ni = 0; ni < 4; ni++) {
                int cl = wn + ni*8 + tq*2;
                ts[ rl     *129 + cl    ] = acc[mi][ni][0];
                ts[ rl     *129 + cl + 1] = acc[mi][ni][1];
                ts[(rl + 8)*129 + cl    ] = acc[mi][ni][2];
                ts[(rl + 8)*129 + cl + 1] = acc[mi][ni][3];
            }
        }
        __syncthreads();
        const int cl  = tid & 127;
        const int rl0 = (tid >> 7) * 64;
        float* Crow = C + (size_t)(n0 + cl)*N + m0 + rl0;
        #pragma unroll
        for (int q = 0; q < 16; q++) {
            float4 v;
            v.x = ts[(rl0 + 4*q    )*129 + cl];
            v.y = ts[(rl0 + 4*q + 1)*129 + cl];
            v.z = ts[(rl0 + 4*q + 2)*129 + cl];
            v.w = ts[(rl0 + 4*q + 3)*129 + cl];
            *(float4*)(Crow + 4*q) = v;
        }
    }
}

// ---------------- batched weight transpose + split (all 7 weights, ONE launch) --
struct TJobs {
    const float* W[7];
    int K[7], N[7], tX[7], base[7], dstOff[7];
    int total;
};

__global__ void transpose_all_kernel(TJobs jobs,
                                     __nv_bfloat16* __restrict__ WTH,
                                     __nv_bfloat16* __restrict__ WTL) {
    __shared__ float tile[32][33];
    int bid = blockIdx.x;
    int j = 0;
    #pragma unroll
    for (int q = 1; q < 7; q++) if (bid >= jobs.base[q]) j = q;
    int local = bid - jobs.base[j];
    int tX = jobs.tX[j];
    int n0 = (local % tX) * 32;
    int k0 = (local / tX) * 32;
    const float* W = jobs.W[j];
    int K = jobs.K[j], N = jobs.N[j];
    __nv_bfloat16* dH = WTH + jobs.dstOff[j];
    __nv_bfloat16* dL = WTL + jobs.dstOff[j];

    int tx = threadIdx.x, ty = threadIdx.y;   // 32 x 8
    #pragma unroll
    for (int i = ty; i < 32; i += 8)
        if (k0 + i < K && n0 + tx < N) tile[i][tx] = W[(size_t)(k0 + i)*N + n0 + tx];
    __syncthreads();
    #pragma unroll
    for (int i = ty; i < 32; i += 8)
        if (n0 + i < N && k0 + tx < K) {
            __nv_bfloat16 hh, ll;
            split1(tile[tx][i], hh, ll);
            dH[(size_t)(n0 + i)*K + k0 + tx] = hh;
            dL[(size_t)(n0 + i)*K + k0 + tx] = ll;
        }
}

// ---------------- elementwise kernels ----------------
__global__ void gather_kernel(const float* __restrict__ x) {
    size_t idx = (size_t)blockIdx.x * blockDim.x + threadIdx.x;  // MROWS*768 exact
    size_t bt = idx / 768; int r = (int)(idx % 768);
    int s = r >> 8, d = r & 255;
    int b = (int)(bt >> 11), t = (int)(bt & 2047);
    float v = x[(((size_t)(b*NSC + s)*TLEN + t) << 8) + d];
    __nv_bfloat16 hh, ll;
    split1(v, hh, ll);
    g_xgP[0][idx] = hh;
    g_xgP[1][idx] = ll;
}

__global__ void flip_kernel() {
    size_t idx = (size_t)blockIdx.x * blockDim.x + threadIdx.x;  // MROWS*512
    size_t bt = idx >> 9; int j = (int)(idx & 511);
    int b = (int)(bt >> 11), t = (int)(bt & 2047);
    size_t src = (((size_t)(b << 11) | (2047 - t)) << 9) | j;
    g_hP2[0][1][idx] = g_hP2[0][0][src];
    g_hP2[1][1][idx] = g_hP2[1][0][src];
}

__global__ void ln512_kernel(const float* __restrict__ in, const float* __restrict__ g,
                             const float* __restrict__ b, float* __restrict__ out) {
    int row = blockIdx.x, tid = threadIdx.x;
    const float* xr = in + (size_t)row * DM2;
    float v0 = xr[tid], v1 = xr[tid + 256];
    float mu = block_reduce(v0 + v1) * (1.f / 512.f);
    float d0 = v0 - mu, d1 = v1 - mu;
    float var = block_reduce(d0*d0 + d1*d1) * (1.f / 512.f);
    float inv = rsqrtf(var + 1e-5f);
    float o0 = d0 * inv * g[tid]       + b[tid];
    float o1 = d1 * inv * g[tid + 256] + b[tid + 256];
    out[(size_t)row*DM2 + tid]       = o0;
    out[(size_t)row*DM2 + tid + 256] = o1;
    __nv_bfloat16 hh, ll;
    split1(o0, hh, ll);
    g_hP2[0][0][(size_t)row*DM2 + tid] = hh;
    g_hP2[1][0][(size_t)row*DM2 + tid] = ll;
    split1(o1, hh, ll);
    g_hP2[0][0][(size_t)row*DM2 + tid + 256] = hh;
    g_hP2[1][0][(size_t)row*DM2 + tid + 256] = ll;
}

__global__ void conv_kernel(const float* __restrict__ cw0, const float* __restrict__ cb0,
                            const float* __restrict__ cw1, const float* __restrict__ cb1) {
    int dir = blockIdx.y;
    size_t idx = (size_t)blockIdx.x * blockDim.x + threadIdx.x;  // MROWS*CCH
    size_t bt = idx / CCH; int c = (int)(idx % CCH);
    int t = (int)(bt & 2047);
    const float* zx = g_zx[dir];
    const float* cw = dir ? cw1 : cw0;
    const float* cb = dir ? cb1 : cb0;
    float acc = cb[c];
    #pragma unroll
    for (int j = 0; j < 4; j++) {
        int tt = t - 3 + j;
        if (tt >= 0)
            acc += cw[c*4 + j] * zx[(bt + j - 3)*(size_t)DPROJ + DIN + c];
    }
    g_xbc[dir][idx] = siluf(acc);
}

__global__ void dtda_kernel(const float* __restrict__ dtb0, const float* __restrict__ Alog0,
                            const float* __restrict__ dtb1, const float* __restrict__ Alog1) {
    int dir = blockIdx.y;
    size_t idx = (size_t)blockIdx.x * blockDim.x + threadIdx.x;  // MROWS*NH
    size_t row = idx >> 4; int hh = (int)(idx & 15);
    const float* dtb = dir ? dtb1 : dtb0;
    const float* Alog = dir ? Alog1 : Alog0;
    float raw = g_zx[dir][row*(size_t)DPROJ + 2*DIN + 2*DS + hh] + dtb[hh];
    float dtv = (raw > 20.f) ? raw : log1pf(expf(raw));
    float dAv = expf(-expf(Alog[hh]) * dtv);
    g_dt[dir][idx] = dtv;
    g_dA[dir][idx] = dAv;
}

// ---------------- sequential SSM scan (sync-free inner loop, f32x2 packed) -------
#define GP 20
__global__ void __launch_bounds__(512) scan_kernel(
    const float* __restrict__ Dh_f, const float* __restrict__ Dh_b)
{
    int blk = blockIdx.x;
    int dir = blk >> 6;
    int bh  = blk & 63;
    int b = bh >> 4, hh = bh & 15;
    const float* __restrict__ xbc = g_xbc[dir];
    const float* __restrict__ zx  = g_zx[dir];
    const float* __restrict__ dtb = g_dt[dir];
    const float* __restrict__ dAb = g_dA[dir];
    float* __restrict__ yout = g_y[dir];
    float Dval = (dir ? Dh_b : Dh_f)[hh];

    const int tid = threadIdx.x;
    const int p  = tid >> 3;     // 0..63
    const int ng = tid & 7;      // 0..7 -> n = ng*16 .. +15

    double S2[8];
    #pragma unroll
    for (int i = 0; i < 8; i++) S2[i] = 0.0;

    __shared__ float sx[8][64], sz[8][64];
    __shared__ float sB[8][8*GP], sC[8][8*GP];
    __shared__ float sdt[8], sdA[8];
    __shared__ float sy[8][64];

    size_t rowbase = (size_t)b * TLEN;

    for (int c0 = 0; c0 < TLEN; c0 += 8) {
        __syncthreads();
        {
            int t = tid >> 6, pp = tid & 63;
            size_t r = rowbase + c0 + t;
            sx[t][pp] = xbc[r*(size_t)CCH + hh*HD + pp];
            sz[t][pp] = zx [r*(size_t)DPROJ + hh*HD + pp];
        }
        #pragma unroll
        for (int q = 0; q < 2; q++) {
            int idx = tid + q*512;
            int t = idx >> 7, n = idx & 127;
            int off = (n >> 4)*GP + (n & 15);
            size_t r = rowbase + c0 + t;
            sB[t][off] = xbc[r*(size_t)CCH + DIN + n];
            sC[t][off] = xbc[r*(size_t)CCH + DIN + DS + n];
        }
        if (tid < 8) {
            size_t r = rowbase + c0 + tid;
            sdt[tid] = dtb[r*NH + hh];
            sdA[tid] = dAb[r*NH + hh];
        }
        __syncthreads();

        #pragma unroll
        for (int t = 0; t < 8; t++) {
            float dtv = sdt[t], dAv = sdA[t];
            float coef = dtv * sx[t][p];
            double dA2, cf2, pa, pb;
            PACK2(dA2, dAv, dAv);
            PACK2(cf2, coef, coef);
            PACK2(pa, 0.f, 0.f);
            PACK2(pb, 0.f, 0.f);
            const double* B2 = (const double*)&sB[t][ng*GP];
            const double* C2 = (const double*)&sC[t][ng*GP];
            #pragma unroll
            for (int i = 0; i < 4; i++) {
                double2 bb = *(const double2*)(B2 + 2*i);
                double2 cc = *(const double2*)(C2 + 2*i);
                double tmp;
                MUL2(tmp, bb.x, cf2);
                FMA2(S2[2*i],     dA2, S2[2*i],     tmp);
                FMA2(pa, S2[2*i],     cc.x, pa);
                MUL2(tmp, bb.y, cf2);
                FMA2(S2[2*i + 1], dA2, S2[2*i + 1], tmp);
                FMA2(pb, S2[2*i + 1], cc.y, pb);
            }
            float alo, ahi, blo, bhi;
            UNPACK2(alo, ahi, pa);
            UNPACK2(blo, bhi, pb);
            float partial = (alo + ahi) + (blo + bhi);
            partial += __shfl_xor_sync(0xffffffffu, partial, 1);
            partial += __shfl_xor_sync(0xffffffffu, partial, 2);
            partial += __shfl_xor_sync(0xffffffffu, partial, 4);
            if (ng == 0) sy[t][p] = partial;
        }
        __syncthreads();

        {
            int t = tid >> 6, pp = tid & 63;
            float y = sy[t][pp];
            float xv = sx[t][pp];
            float zv = sz[t][pp];
            float yv = (y + Dval * xv) * siluf(zv);
            yout[(rowbase + c0 + t)*(size_t)DIN + hh*HD + pp] = yv;
        }
    }
}

__global__ void rms_kernel(const float* __restrict__ w0, const float* __restrict__ w1,
                           __nv_bfloat16* __restrict__ yH, __nv_bfloat16* __restrict__ yL) {
    int rb = blockIdx.x;                  // 0 .. 2*MROWS-1
    int dir = rb >> 13, row = rb & (MROWS - 1);
    int tid = threadIdx.x;
    const float* yr = g_y[dir] + (size_t)row * DIN;
    const float* w = dir ? w1 : w0;
    size_t obase = (size_t)dir*MROWS*DIN + (size_t)row*DIN;
    float v[4]; float ss = 0.f;
    #pragma unroll
    for (int i = 0; i < 4; i++) { v[i] = yr[tid + i*256]; ss += v[i]*v[i]; }
    ss = block_reduce(ss);
    float inv = rsqrtf(ss * (1.f/1024.f) + 1e-5f);
    #pragma unroll
    for (int i = 0; i < 4; i++) {
        float o = v[i] * inv * w[tid + i*256];
        __nv_bfloat16 hh, ll;
        split1(o, hh, ll);
        yH[obase + tid + i*256] = hh;
        yL[obase + tid + i*256] = ll;
    }
}

__global__ void combine_kernel() {
    size_t idx = (size_t)blockIdx.x * blockDim.x + threadIdx.x;  // MROWS*512
    size_t bt = idx >> 9; int j = (int)(idx & 511);
    int b = (int)(bt >> 11), t = (int)(bt & 2047);
    float hv = g_h[idx];
    float ob = g_od[1][(((size_t)(b << 11) | (2047 - t)) << 9) | j];
    float u = (g_od[0][idx] + ob) * siluf(hv);
    __nv_bfloat16 hh, ll;
    split1(u, hh, ll);
    g_uP[0][idx] = hh;
    g_uP[1][idx] = ll;
}

__global__ void lnpost_kernel(const float* __restrict__ vbuf, const float* __restrict__ g,
                              const float* __restrict__ b, float* __restrict__ outdst) {
    int row = blockIdx.x, tid = threadIdx.x;
    float x = vbuf[(size_t)row*DMODEL + tid];
    float mu = block_reduce(x) * (1.f/256.f);
    float d = x - mu;
    float var = block_reduce(d*d) * (1.f/256.f);
    float o = d * rsqrtf(var + 1e-5f) * g[tid] + b[tid] + g_xp[(size_t)row*DMODEL + tid];
    outdst[(size_t)row*DMODEL + tid] = o;
    float ss = block_reduce(o*o);
    float sc = 1.f / fmaxf(sqrtf(ss), 1e-12f);
    float fnv = o * sc;
    __nv_bfloat16 hh, ll;
    split1(fnv, hh, ll);
    g_fnP[0][(size_t)row*DMODEL + tid] = hh;
    g_fnP[1][(size_t)row*DMODEL + tid] = ll;
}

// ---------------- launcher ----------------
extern "C" void kernel_launch(void* const* d_in, const int* in_sizes, int n_in,
                              void* d_out, int out_size)
{
    const float* x       = (const float*)d_in[0];
    const float* Wp      = (const float*)d_in[1];
    const float* bp      = (const float*)d_in[2];
    const float* Wpre    = (const float*)d_in[3];
    const float* bpre    = (const float*)d_in[4];
    const float* lnpre_g = (const float*)d_in[5];
    const float* lnpre_b = (const float*)d_in[6];
    const float* Wpost   = (const float*)d_in[7];
    const float* bpost   = (const float*)d_in[8];
    const float* lnpost_g= (const float*)d_in[9];
    const float* lnpost_b= (const float*)d_in[10];
    const float* Win[2]   = {(const float*)d_in[11], (const float*)d_in[19]};
    const float* convw[2] = {(const float*)d_in[12], (const float*)d_in[20]};
    const float* convb[2] = {(const float*)d_in[13], (const float*)d_in[21]};
    const float* dtb[2]   = {(const float*)d_in[14], (const float*)d_in[22]};
    const float* Alog[2]  = {(const float*)d_in[15], (const float*)d_in[23]};
    const float* Dh[2]    = {(const float*)d_in[16], (const float*)d_in[24]};
    const float* normw[2] = {(const float*)d_in[17], (const float*)d_in[25]};
    const float* Wout[2]  = {(const float*)d_in[18], (const float*)d_in[26]};

    static bool attr_done = false;
    if (!attr_done) {
        cudaFuncSetAttribute(tgemmB, cudaFuncAttributeMaxDynamicSharedMemorySize, SMEM_ALL);
        attr_done = true;
    }

    float *xp, *pre, *h, *zxb, *odb, *v;
    __nv_bfloat16 *xgP, *xpP, *hP2, *yP, *uP, *fnP, *wtP;
    cudaGetSymbolAddress((void**)&xp,  g_xp);
    cudaGetSymbolAddress((void**)&pre, g_pre);
    cudaGetSymbolAddress((void**)&h,   g_h);
    cudaGetSymbolAddress((void**)&zxb, g_zx);
    cudaGetSymbolAddress((void**)&odb, g_od);
    cudaGetSymbolAddress((void**)&v,   g_v);
    cudaGetSymbolAddress((void**)&xgP, g_xgP);
    cudaGetSymbolAddress((void**)&xpP, g_xpP);
    cudaGetSymbolAddress((void**)&hP2, g_hP2);
    cudaGetSymbolAddress((void**)&yP,  g_yP);
    cudaGetSymbolAddress((void**)&uP,  g_uP);
    cudaGetSymbolAddress((void**)&fnP, g_fnP);
    cudaGetSymbolAddress((void**)&wtP, g_wtP);

    float* zx0 = zxb;
    float* od0 = odb;

    const size_t PXG = (size_t)MROWS*768;
    const size_t PXP = (size_t)MROWS*DMODEL;
    const size_t PH  = (size_t)MROWS*DM2;
    const size_t PY  = 2*(size_t)MROWS*DIN;
    const size_t PW  = 3883008;
    __nv_bfloat16 *xgH = xgP,          *xgL = xgP + PXG;
    __nv_bfloat16 *xpH = xpP,          *xpL = xpP + PXP;
    __nv_bfloat16 *hH  = hP2,          *hL  = hP2 + 2*PH;  // [plane][dir] layout
    __nv_bfloat16 *yH  = yP,           *yL  = yP  + PY;
    __nv_bfloat16 *uH  = uP,           *uL  = uP  + PH;
    __nv_bfloat16 *fnH = fnP,          *fnL = fnP + PXP;
    __nv_bfloat16 *wH  = wtP,          *wL  = wtP + PW;

    float* out  = (float*)d_out;
    float* attn = out + (size_t)MROWS*DMODEL;

    dim3 tb(32, 8);
    // 0. transpose + split all 7 weights in ONE launch
    TJobs jobs;
    const float* Ws[7]   = {Wp, Wpre, Win[0], Win[1], Wout[0], Wout[1], Wpost};
    const int   Ks[7]    = {768, DMODEL, DM2, DM2, DIN, DIN, DM2};
    const int   Ns[7]    = {DMODEL, DM2, DPROJ, DPROJ, DM2, DM2, DMODEL};
    const int   Offs[7]  = {OFF_WPT, OFF_WPRET, OFF_WINT0, OFF_WINT1, OFF_WOUTT0, OFF_WOUTT1, OFF_WPOSTT};
    int base = 0;
    for (int j = 0; j < 7; j++) {
        jobs.W[j] = Ws[j]; jobs.K[j] = Ks[j]; jobs.N[j] = Ns[j];
        jobs.tX[j] = (Ns[j] + 31) / 32;
        jobs.base[j] = base;
        jobs.dstOff[j] = Offs[j];
        base += jobs.tX[j] * ((Ks[j] + 31) / 32);
    }
    jobs.total = base;
    transpose_all_kernel<<<base, tb>>>(jobs, wH, wL);

    // 1. gather (+split) + input projection (epilogue also writes xp planes)
    gather_kernel<<<MROWS*768/256, 256>>>(x);
    tgemmB<<<dim3(2, MROWS/128), 256, SMEM_ALL>>>(
        xgH, xgL, wH + OFF_WPT, wL + OFF_WPT, bp, xp, xpH, xpL, MROWS, DMODEL, 768, 0, 0, 0, 0);
    // 2. pre-layernorm
    tgemmB<<<dim3(4, MROWS/128), 256, SMEM_ALL>>>(
        xpH, xpL, wH + OFF_WPRET, wL + OFF_WPRET, bpre, pre, nullptr, nullptr, MROWS, DM2, DMODEL, 0, 0, 0, 0);
    ln512_kernel<<<MROWS, 256>>>(pre, lnpre_g, lnpre_b, h);
    flip_kernel<<<MROWS*DM2/256, 256>>>();
    // 3. mamba in-projections (both directions in ONE batched launch, z=2)
    tgemmB<<<dim3(19, MROWS/128, 2), 256, SMEM_ALL>>>(
        hH, hL, wH + OFF_WINT0, wL + OFF_WINT0, nullptr, zx0, nullptr, nullptr,
        MROWS, DPROJ, DM2, PH, (size_t)DPROJ*DM2, (size_t)MROWS*DPROJ, 0);
    // 4. conv + dt/dA (both dirs batched)
    conv_kernel<<<dim3(MROWS*CCH/256, 2), 256>>>(convw[0], convb[0], convw[1], convb[1]);
    dtda_kernel<<<dim3(MROWS*NH/256, 2), 256>>>(dtb[0], Alog[0], dtb[1], Alog[1]);
    // 5. both scans concurrently
    scan_kernel<<<128, 512>>>(Dh[0], Dh[1]);
    // 6. RMS-norm (+split, both dirs in one launch) + out-projections (z=2)
    rms_kernel<<<2*MROWS, 256>>>(normw[0], normw[1], yH, yL);
    tgemmB<<<dim3(4, MROWS/128, 2), 256, SMEM_ALL>>>(
        yH, yL, wH + OFF_WOUTT0, wL + OFF_WOUTT0, nullptr, od0, nullptr, nullptr,
        MROWS, DM2, DIN, (size_t)MROWS*DIN, (size_t)DIN*DM2, (size_t)MROWS*DM2, 0);
    // 7. gated combine (+split) + post projection + post-LN(+residual) + fn planes
    combine_kernel<<<MROWS*DM2/256, 256>>>();
    tgemmB<<<dim3(2, MROWS/128), 256, SMEM_ALL>>>(
        uH, uL, wH + OFF_WPOSTT, wL + OFF_WPOSTT, bpost, v, nullptr, nullptr, MROWS, DMODEL, DM2, 0, 0, 0, 0);
    lnpost_kernel<<<MROWS, 256>>>(v, lnpost_g, lnpost_b, out);
    // 8. attn = fn @ fn^T per batch (symmetric: upper blocks computed, mirror
    //    written from the same CTA via smem transpose — no extra pass)
    tgemmB<<<dim3(16, 16, BATCH), 256, SMEM_ALL>>>(
        fnH, fnL, fnH, fnL, nullptr, attn, nullptr, nullptr, TLEN, TLEN, DMODEL,
        (size_t)TLEN*DMODEL, (size_t)TLEN*DMODEL, (size_t)TLEN*TLEN, 1);
}